// round 16
// baseline (speedup 1.0000x reference)
#include <cuda_runtime.h>
#include <cuda_fp16.h>

#define NN 50000
#define EE 400000
#define CC 128

__device__ float  g_h   [NN * CC];
__device__ float  g_hn  [NN * CC];
__device__ float  g_x   [NN * 3];
__device__ float  g_xn  [NN * 3];
__device__ __half g_Ph0 [(size_t)NN * 512];   // src_n | src_c (fp16, random gathers)
__device__ __half g_Ph1 [(size_t)NN * 512];
__device__ float  g_Pf0 [(size_t)NN * 512];   // dst_n | dst_c (fp32, cache-hot)
__device__ float  g_Pf1 [(size_t)NN * 512];
__device__ float  g_Wsw [8 * 64 * 256];
__device__ float  g_bp  [8 * 256];
__device__ float  g_Bp  [16 * 2 * 32768];
__device__ float  g_Wn2sw[4 * 2 * 32768];
__device__ float  g_aggS[(size_t)NN * 256];
__device__ int    g_cnt [NN];
__device__ int    g_off [NN];
__device__ int    g_srcS[EE];
__device__ int    g_dstS[EE];
__device__ float  g_distS[EE];

// silu via single-MUFU hardware tanh: silu(v) = v * (0.5*tanh(v/2) + 0.5)
__device__ __forceinline__ float siluf(float v) {
    float t;
    asm("tanh.approx.f32 %0, %1;" : "=f"(t) : "f"(v * 0.5f));
    return v * fmaf(0.5f, t, 0.5f);
}

__device__ __forceinline__ unsigned tf32r(float v) {
    unsigned u;
    asm("cvt.rna.tf32.f32 %0, %1;" : "=r"(u) : "f"(v));
    return u;
}

__device__ __forceinline__ void mma8(float* C, unsigned a0, unsigned a1, unsigned a2, unsigned a3,
                                     unsigned b0, unsigned b1) {
    asm volatile("mma.sync.aligned.m16n8k8.row.col.f32.tf32.tf32.f32 "
                 "{%0,%1,%2,%3}, {%4,%5,%6,%7}, {%8,%9}, {%0,%1,%2,%3};"
                 : "+f"(C[0]), "+f"(C[1]), "+f"(C[2]), "+f"(C[3])
                 : "r"(a0), "r"(a1), "r"(a2), "r"(a3), "r"(b0), "r"(b1));
}

__device__ __forceinline__ void redv2(float* addr, float v0, float v1) {
    asm volatile("red.global.add.v2.f32 [%0], {%1,%2};" :: "l"(addr), "f"(v0), "f"(v1) : "memory");
}

__device__ __forceinline__ int bswz(int k, int n) {
    return (((k >> 3) * 16 + (n >> 4)) << 7)
         + ((n & 7) << 4) + ((k & 3) << 2) + (((n >> 3) & 1) << 1) + ((k >> 2) & 1);
}
__device__ __forceinline__ int bswz128(int k, int n) {
    return (((k >> 3) * 8 + (n >> 4)) << 7)
         + ((n & 7) << 4) + ((k & 3) << 2) + (((n >> 3) & 1) << 1) + ((k >> 2) & 1);
}

// ---------- sort by dst ----------
__global__ void hist_kernel(const int* __restrict__ dstIdx, int* __restrict__ cnt) {
    int e = blockIdx.x * blockDim.x + threadIdx.x;
    if (e < EE) atomicAdd(&cnt[dstIdx[e]], 1);
}

__global__ void scan_kernel(const int* __restrict__ cnt, int* __restrict__ off) {
    __shared__ int sa[1024], sb[1024];
    int t = threadIdx.x;
    int base = t * 49;
    int s = 0;
    for (int i = 0; i < 49; i++) { int r = base + i; if (r < NN) s += cnt[r]; }
    sa[t] = s;
    __syncthreads();
    int* in = sa; int* out = sb;
    for (int d = 1; d < 1024; d <<= 1) {
        out[t] = (t >= d) ? in[t] + in[t - d] : in[t];
        __syncthreads();
        int* tmp = in; in = out; out = tmp;
    }
    int run = (t > 0) ? in[t - 1] : 0;
    for (int i = 0; i < 49; i++) {
        int r = base + i;
        if (r < NN) { off[r] = run; run += cnt[r]; }
    }
}

__global__ void scatter_kernel(const int* __restrict__ srcIdx, const int* __restrict__ dstIdx,
                               const float* __restrict__ dist, int* __restrict__ off,
                               int* __restrict__ srcS, int* __restrict__ dstS,
                               float* __restrict__ distS) {
    int e = blockIdx.x * blockDim.x + threadIdx.x;
    if (e < EE) {
        int d = dstIdx[e];
        int pos = atomicAdd(&off[d], 1);
        int blk = pos >> 5, r = pos & 31;
        int mt = r >> 4, j = r & 15;
        int nr = mt * 16 + ((j & 1) << 3) + (j >> 1);
        int p = blk * 32 + nr;
        srcS[p] = srcIdx[e];
        dstS[p] = d;
        distS[p] = dist[e];
    }
}

// ---------- prep kernels ----------
__global__ void prep_kernel(const float* __restrict__ We2, const float* __restrict__ be2,
                            const float* __restrict__ Wn1, const float* __restrict__ bn1,
                            const float* __restrict__ Wc1, const float* __restrict__ bc1,
                            float* __restrict__ Wsw, float* __restrict__ bp)
{
    int b = blockIdx.x, l = b >> 1, path = b & 1;
    const float* W1 = (path ? Wc1 : Wn1) + (size_t)l * 320 * 256;
    const float* bb = (path ? bc1 : bn1) + l * 256;
    const float* W2 = We2 + l * 64 * 64;
    const float* b2 = be2 + l * 64;
    int c = threadIdx.x;
    float acc[64];
#pragma unroll
    for (int k = 0; k < 64; k++) acc[k] = 0.f;
    float bacc = bb[c];
    for (int q = 0; q < 64; q++) {
        float w = W1[(size_t)(256 + q) * 256 + c];
        bacc += b2[q] * w;
#pragma unroll
        for (int k = 0; k < 64; k++) acc[k] += W2[k * 64 + q] * w;
    }
#pragma unroll
    for (int k = 0; k < 64; k++)
        Wsw[(size_t)b * 16384 + bswz(k, c)] = __uint_as_float(tf32r(acc[k]));
    bp[b * 256 + c] = bacc;
}

__global__ void prep2_kernel(const float* __restrict__ Wn1, const float* __restrict__ Wc1,
                             float* __restrict__ Bp)
{
    int b = blockIdx.x;
    int l = b >> 2, q = b & 3;
    const float* W = (q < 2 ? Wn1 : Wc1) + (size_t)l * 320 * 256 + (size_t)((q & 1) * 128) * 256;
    int c = threadIdx.x;
    float* hiP = Bp + (size_t)b * 65536;
    float* loP = hiP + 32768;
    for (int k = 0; k < 128; k++) {
        float v = W[(size_t)k * 256 + c];
        float hf = __uint_as_float(tf32r(v));
        unsigned lo = tf32r(v - hf);
        int idx = bswz(k, c);
        hiP[idx] = hf;
        loP[idx] = __uint_as_float(lo);
    }
}

__global__ void prep3_kernel(const float* __restrict__ Wn2, float* __restrict__ Wn2sw)
{
    int l = blockIdx.x;
    const float* W = Wn2 + (size_t)l * 256 * 128;
    float* hiP = Wn2sw + (size_t)l * 65536;
    float* loP = hiP + 32768;
    int c = threadIdx.x;
    for (int k = 0; k < 256; k++) {
        float v = W[(size_t)k * 128 + c];
        float hf = __uint_as_float(tf32r(v));
        unsigned lo = tf32r(v - hf);
        int idx = bswz128(k, c);
        hiP[idx] = hf;
        loP[idx] = __uint_as_float(lo);
    }
}

// ---------- proj via TF32 mma; src->fp16 Ph, dst->fp32 Pf ----------
// q mapping: 0 = Wn1-src (Ph col 0), 1 = Wn1-dst (Pf col 0),
//            2 = Wc1-src (Ph col 256), 3 = Wc1-dst (Pf col 256)
__global__ void __launch_bounds__(256) proj2_kernel(const float* __restrict__ h,
                                                    const float* __restrict__ Bl,
                                                    __half* __restrict__ Ph,
                                                    float* __restrict__ Pf)
{
    __shared__ float As[64 * 132];
    int bx = blockIdx.x;
    int q = blockIdx.y >> 1, half = blockIdx.y & 1;
    int tid = threadIdx.x;
    int lane = tid & 31, w = tid >> 5;
    int wm = w & 1, wn = w >> 1;
    int gid = lane >> 2, tig = lane & 3;

#pragma unroll
    for (int i = 0; i < 8; i++) {
        int f = i * 256 + tid;
        int row = f >> 5, c4 = (f & 31) << 2;
        int grow = bx * 64 + row;
        float4 v = make_float4(0.f, 0.f, 0.f, 0.f);
        if (grow < NN) v = *(const float4*)(h + (size_t)grow * 128 + c4);
        *(float4*)(As + row * 132 + c4) = v;
    }
    __syncthreads();

    const float* Bhi = Bl + (size_t)q * 65536;
    const float* Blo = Bhi + 32768;
    float C[32];
#pragma unroll
    for (int i = 0; i < 32; i++) C[i] = 0.f;

#pragma unroll 4
    for (int kk = 0; kk < 16; kk++) {
        unsigned ah[2][4], al[2][4];
#pragma unroll
        for (int mt = 0; mt < 2; mt++) {
            int r0 = wm * 32 + mt * 16 + gid;
            int r1 = r0 + 8;
            float v00 = As[r0 * 132 + kk * 8 + tig];
            float v10 = As[r1 * 132 + kk * 8 + tig];
            float v01 = As[r0 * 132 + kk * 8 + tig + 4];
            float v11 = As[r1 * 132 + kk * 8 + tig + 4];
            ah[mt][0] = tf32r(v00); ah[mt][1] = tf32r(v10);
            ah[mt][2] = tf32r(v01); ah[mt][3] = tf32r(v11);
            al[mt][0] = tf32r(v00 - __uint_as_float(ah[mt][0]));
            al[mt][1] = tf32r(v10 - __uint_as_float(ah[mt][1]));
            al[mt][2] = tf32r(v01 - __uint_as_float(ah[mt][2]));
            al[mt][3] = tf32r(v11 - __uint_as_float(ah[mt][3]));
        }
#pragma unroll
        for (int jp = 0; jp < 2; jp++) {
            float4 bb = *(const float4*)(Bhi + ((size_t)(kk * 16 + half * 8 + wn * 2 + jp) << 7) + lane * 4);
#pragma unroll
            for (int mt = 0; mt < 2; mt++) {
                float* Ce = C + (mt * 4 + jp * 2) * 4;
                float* Co = C + (mt * 4 + jp * 2 + 1) * 4;
                mma8(Ce, ah[mt][0], ah[mt][1], ah[mt][2], ah[mt][3],
                     __float_as_uint(bb.x), __float_as_uint(bb.y));
                mma8(Co, ah[mt][0], ah[mt][1], ah[mt][2], ah[mt][3],
                     __float_as_uint(bb.z), __float_as_uint(bb.w));
                mma8(Ce, al[mt][0], al[mt][1], al[mt][2], al[mt][3],
                     __float_as_uint(bb.x), __float_as_uint(bb.y));
                mma8(Co, al[mt][0], al[mt][1], al[mt][2], al[mt][3],
                     __float_as_uint(bb.z), __float_as_uint(bb.w));
            }
        }
    }
#pragma unroll 4
    for (int kk = 0; kk < 16; kk++) {
        unsigned ah[2][4];
#pragma unroll
        for (int mt = 0; mt < 2; mt++) {
            int r0 = wm * 32 + mt * 16 + gid;
            int r1 = r0 + 8;
            ah[mt][0] = tf32r(As[r0 * 132 + kk * 8 + tig]);
            ah[mt][1] = tf32r(As[r1 * 132 + kk * 8 + tig]);
            ah[mt][2] = tf32r(As[r0 * 132 + kk * 8 + tig + 4]);
            ah[mt][3] = tf32r(As[r1 * 132 + kk * 8 + tig + 4]);
        }
#pragma unroll
        for (int jp = 0; jp < 2; jp++) {
            float4 bb = *(const float4*)(Blo + ((size_t)(kk * 16 + half * 8 + wn * 2 + jp) << 7) + lane * 4);
#pragma unroll
            for (int mt = 0; mt < 2; mt++) {
                mma8(C + (mt * 4 + jp * 2) * 4, ah[mt][0], ah[mt][1], ah[mt][2], ah[mt][3],
                     __float_as_uint(bb.x), __float_as_uint(bb.y));
                mma8(C + (mt * 4 + jp * 2 + 1) * 4, ah[mt][0], ah[mt][1], ah[mt][2], ah[mt][3],
                     __float_as_uint(bb.z), __float_as_uint(bb.w));
            }
        }
    }

    int isDst = q & 1;
    int colbase = (q >> 1) * 256;
#pragma unroll
    for (int mt = 0; mt < 2; mt++) {
        int r0 = bx * 64 + wm * 32 + mt * 16 + gid;
        int r1 = r0 + 8;
#pragma unroll
        for (int j = 0; j < 4; j++) {
            int col = colbase + half * 128 + wn * 32 + j * 8 + tig * 2;
            if (isDst) {
                if (r0 < NN)
                    *(float2*)(Pf + (size_t)r0 * 512 + col) =
                        make_float2(C[(mt * 4 + j) * 4 + 0], C[(mt * 4 + j) * 4 + 1]);
                if (r1 < NN)
                    *(float2*)(Pf + (size_t)r1 * 512 + col) =
                        make_float2(C[(mt * 4 + j) * 4 + 2], C[(mt * 4 + j) * 4 + 3]);
            } else {
                if (r0 < NN)
                    *(__half2*)(Ph + (size_t)r0 * 512 + col) =
                        __floats2half2_rn(C[(mt * 4 + j) * 4 + 0], C[(mt * 4 + j) * 4 + 1]);
                if (r1 < NN)
                    *(__half2*)(Ph + (size_t)r1 * 512 + col) =
                        __floats2half2_rn(C[(mt * 4 + j) * 4 + 2], C[(mt * 4 + j) * 4 + 3]);
            }
        }
    }
}

// ---------- path n edge kernel (src fp16, dst fp32) ----------
__global__ void __launch_bounds__(256, 4) edgen_kernel(
    const int* __restrict__ srcS, const int* __restrict__ dstS,
    const float* __restrict__ distS,
    const float* __restrict__ We1l, const float* __restrict__ be1l,
    const float* __restrict__ Wswn, const float* __restrict__ bpn,
    const __half* __restrict__ Ph, const float* __restrict__ Pf,
    float* __restrict__ aggS)
{
    __shared__ float Ea[32 * 68];
    __shared__ float bpS[256];
    __shared__ int sIdx[32], dIdx[32];

    int tid = threadIdx.x;
    int lane = tid & 31, w = tid >> 5;
    int mt = w & 1, nt = w >> 1;
    int gid = lane >> 2, tig = lane & 3;
    int e0 = blockIdx.x * 32;

    if (tid < 32) { sIdx[tid] = srcS[e0 + tid]; dIdx[tid] = dstS[e0 + tid]; }
    bpS[tid] = bpn[tid];
    {
        int m = tid >> 3, seg = tid & 7;
        float d = distS[e0 + m];
#pragma unroll
        for (int kk = 0; kk < 8; kk++) {
            int k = seg * 8 + kk;
            Ea[m * 68 + k] = __uint_as_float(tf32r(siluf(fmaf(d, We1l[k], be1l[k]))));
        }
    }
    __syncthreads();

    int r0 = mt * 16 + gid, r1 = r0 + 8;
    int s0 = sIdx[r0], d0 = dIdx[r0];
    int s1 = sIdx[r1], d1 = dIdx[r1];

    float C[32];
#pragma unroll
    for (int i = 0; i < 32; i++) C[i] = 0.f;
#pragma unroll
    for (int kk = 0; kk < 8; kk++) {
        unsigned a0 = __float_as_uint(Ea[r0 * 68 + kk * 8 + tig]);
        unsigned a1 = __float_as_uint(Ea[r1 * 68 + kk * 8 + tig]);
        unsigned a2 = __float_as_uint(Ea[r0 * 68 + kk * 8 + tig + 4]);
        unsigned a3 = __float_as_uint(Ea[r1 * 68 + kk * 8 + tig + 4]);
#pragma unroll
        for (int jp = 0; jp < 4; jp++) {
            float4 bb = *(const float4*)(Wswn + ((size_t)(kk * 16 + nt * 4 + jp) << 7) + lane * 4);
            mma8(C + (jp * 2) * 4, a0, a1, a2, a3, __float_as_uint(bb.x), __float_as_uint(bb.y));
            mma8(C + (jp * 2 + 1) * 4, a0, a1, a2, a3, __float_as_uint(bb.z), __float_as_uint(bb.w));
        }
    }
#pragma unroll
    for (int j = 0; j < 8; j++) {
        int cc = (nt * 8 + j) * 8 + tig * 2;
        float2 bb = *(const float2*)(bpS + cc);
        float2 ps = __half22float2(*(const __half2*)(Ph + (size_t)s0 * 512 + cc));
        float2 pd = *(const float2*)(Pf + (size_t)d0 * 512 + cc);
        float v0 = siluf(C[j * 4 + 0] + bb.x + ps.x + pd.x);
        float v1 = siluf(C[j * 4 + 1] + bb.y + ps.y + pd.y);
        ps = __half22float2(*(const __half2*)(Ph + (size_t)s1 * 512 + cc));
        pd = *(const float2*)(Pf + (size_t)d1 * 512 + cc);
        float w0 = siluf(C[j * 4 + 2] + bb.x + ps.x + pd.x);
        float w1 = siluf(C[j * 4 + 3] + bb.y + ps.y + pd.y);
        if (d0 == d1) {
            redv2(aggS + (size_t)d0 * 256 + cc, v0 + w0, v1 + w1);
        } else {
            redv2(aggS + (size_t)d0 * 256 + cc, v0, v1);
            redv2(aggS + (size_t)d1 * 256 + cc, w0, w1);
        }
    }
}

// ---------- path c edge kernel (src fp16, dst fp32) ----------
__global__ void __launch_bounds__(256, 4) edgec_kernel(
    const int* __restrict__ srcS, const int* __restrict__ dstS,
    const float* __restrict__ distS,
    const float* __restrict__ We1l, const float* __restrict__ be1l,
    const float* __restrict__ Wswc, const float* __restrict__ bpc,
    const float* __restrict__ Wc2l,
    const __half* __restrict__ Ph, const float* __restrict__ Pf,
    const float* __restrict__ x, float* __restrict__ xn)
{
    __shared__ float Ea[32 * 68];
    __shared__ float bpS[256];
    __shared__ float Wc2s[256];
    __shared__ float cwP[128];
    __shared__ int sIdx[32], dIdx[32];

    int tid = threadIdx.x;
    int lane = tid & 31, w = tid >> 5;
    int mt = w & 1, nt = w >> 1;
    int gid = lane >> 2, tig = lane & 3;
    int e0 = blockIdx.x * 32;

    if (tid < 32) { sIdx[tid] = srcS[e0 + tid]; dIdx[tid] = dstS[e0 + tid]; }
    bpS[tid] = bpc[tid];
    Wc2s[tid] = Wc2l[tid];
    {
        int m = tid >> 3, seg = tid & 7;
        float d = distS[e0 + m];
#pragma unroll
        for (int kk = 0; kk < 8; kk++) {
            int k = seg * 8 + kk;
            Ea[m * 68 + k] = __uint_as_float(tf32r(siluf(fmaf(d, We1l[k], be1l[k]))));
        }
    }
    __syncthreads();

    int r0 = mt * 16 + gid, r1 = r0 + 8;
    int s0 = sIdx[r0], d0 = dIdx[r0];
    int s1 = sIdx[r1], d1 = dIdx[r1];

    float C[32];
#pragma unroll
    for (int i = 0; i < 32; i++) C[i] = 0.f;
#pragma unroll
    for (int kk = 0; kk < 8; kk++) {
        unsigned a0 = __float_as_uint(Ea[r0 * 68 + kk * 8 + tig]);
        unsigned a1 = __float_as_uint(Ea[r1 * 68 + kk * 8 + tig]);
        unsigned a2 = __float_as_uint(Ea[r0 * 68 + kk * 8 + tig + 4]);
        unsigned a3 = __float_as_uint(Ea[r1 * 68 + kk * 8 + tig + 4]);
#pragma unroll
        for (int jp = 0; jp < 4; jp++) {
            float4 bb = *(const float4*)(Wswc + ((size_t)(kk * 16 + nt * 4 + jp) << 7) + lane * 4);
            mma8(C + (jp * 2) * 4, a0, a1, a2, a3, __float_as_uint(bb.x), __float_as_uint(bb.y));
            mma8(C + (jp * 2 + 1) * 4, a0, a1, a2, a3, __float_as_uint(bb.z), __float_as_uint(bb.w));
        }
    }
    float p0 = 0.f, p1 = 0.f;
#pragma unroll
    for (int j = 0; j < 8; j++) {
        int cc = (nt * 8 + j) * 8 + tig * 2;
        float2 bb = *(const float2*)(bpS + cc);
        float2 wc = *(const float2*)(Wc2s + cc);
        float2 ps = __half22float2(*(const __half2*)(Ph + (size_t)s0 * 512 + 256 + cc));
        float2 pd = *(const float2*)(Pf + (size_t)d0 * 512 + 256 + cc);
        p0 += siluf(C[j * 4 + 0] + bb.x + ps.x + pd.x) * wc.x
            + siluf(C[j * 4 + 1] + bb.y + ps.y + pd.y) * wc.y;
        ps = __half22float2(*(const __half2*)(Ph + (size_t)s1 * 512 + 256 + cc));
        pd = *(const float2*)(Pf + (size_t)d1 * 512 + 256 + cc);
        p1 += siluf(C[j * 4 + 2] + bb.x + ps.x + pd.x) * wc.x
            + siluf(C[j * 4 + 3] + bb.y + ps.y + pd.y) * wc.y;
    }
    p0 += __shfl_xor_sync(0xffffffffu, p0, 1);
    p0 += __shfl_xor_sync(0xffffffffu, p0, 2);
    p1 += __shfl_xor_sync(0xffffffffu, p1, 1);
    p1 += __shfl_xor_sync(0xffffffffu, p1, 2);
    if (tig == 0) {
        cwP[r0 * 4 + nt] = p0;
        cwP[r1 * 4 + nt] = p1;
    }
    __syncthreads();
    if (tid < 32) {
        float cw = cwP[tid * 4] + cwP[tid * 4 + 1] + cwP[tid * 4 + 2] + cwP[tid * 4 + 3];
        int s = sIdx[tid], dd = dIdx[tid];
        float u0 = cw * (x[(size_t)s * 3 + 0] - x[(size_t)dd * 3 + 0]);
        float u1 = cw * (x[(size_t)s * 3 + 1] - x[(size_t)dd * 3 + 1]);
        float u2 = cw * (x[(size_t)s * 3 + 2] - x[(size_t)dd * 3 + 2]);
        atomicAdd(&xn[(size_t)dd * 3 + 0], u0);
        atomicAdd(&xn[(size_t)dd * 3 + 1], u1);
        atomicAdd(&xn[(size_t)dd * 3 + 2], u2);
    }
}

// ---------- nupd2: hn = h + aggS @ Wn2 + deg*bn2; zeroes aggS after read ----------
__global__ void __launch_bounds__(256) nupd2_kernel(float* __restrict__ A,
                                                    const float* __restrict__ Bl,
                                                    const float* __restrict__ bn2l,
                                                    const float* __restrict__ hprev,
                                                    const int* __restrict__ deg,
                                                    float* __restrict__ hn)
{
    __shared__ float As[64 * 132];
    int bx = blockIdx.x;
    int tid = threadIdx.x;
    int lane = tid & 31, w = tid >> 5;
    int wm = w & 1, wn = w >> 1;
    int gid = lane >> 2, tig = lane & 3;

    const float* Bhi = Bl;
    const float* Blo = Bl + 32768;
    float C[32];
#pragma unroll
    for (int i = 0; i < 32; i++) C[i] = 0.f;

#pragma unroll
    for (int s = 0; s < 2; s++) {
        __syncthreads();
#pragma unroll
        for (int i = 0; i < 8; i++) {
            int f = i * 256 + tid;
            int row = f >> 5, c4 = (f & 31) << 2;
            int grow = bx * 64 + row;
            float4 v = make_float4(0.f, 0.f, 0.f, 0.f);
            if (grow < NN) {
                float4* ap = (float4*)(A + (size_t)grow * 256 + s * 128 + c4);
                v = *ap;
                *ap = make_float4(0.f, 0.f, 0.f, 0.f);   // zero for next layer
            }
            *(float4*)(As + row * 132 + c4) = v;
        }
        __syncthreads();

#pragma unroll 4
        for (int kk = 0; kk < 16; kk++) {
            unsigned ah[2][4], al[2][4];
#pragma unroll
            for (int mt = 0; mt < 2; mt++) {
                int r0 = wm * 32 + mt * 16 + gid;
                int r1 = r0 + 8;
                float v00 = As[r0 * 132 + kk * 8 + tig];
                float v10 = As[r1 * 132 + kk * 8 + tig];
                float v01 = As[r0 * 132 + kk * 8 + tig + 4];
                float v11 = As[r1 * 132 + kk * 8 + tig + 4];
                ah[mt][0] = tf32r(v00); ah[mt][1] = tf32r(v10);
                ah[mt][2] = tf32r(v01); ah[mt][3] = tf32r(v11);
                al[mt][0] = tf32r(v00 - __uint_as_float(ah[mt][0]));
                al[mt][1] = tf32r(v10 - __uint_as_float(ah[mt][1]));
                al[mt][2] = tf32r(v01 - __uint_as_float(ah[mt][2]));
                al[mt][3] = tf32r(v11 - __uint_as_float(ah[mt][3]));
            }
#pragma unroll
            for (int jp = 0; jp < 2; jp++) {
                int chunk = (s * 16 + kk) * 8 + wn * 2 + jp;
                float4 bb = *(const float4*)(Bhi + ((size_t)chunk << 7) + lane * 4);
#pragma unroll
                for (int mt = 0; mt < 2; mt++) {
                    float* Ce = C + (mt * 4 + jp * 2) * 4;
                    float* Co = C + (mt * 4 + jp * 2 + 1) * 4;
                    mma8(Ce, ah[mt][0], ah[mt][1], ah[mt][2], ah[mt][3],
                         __float_as_uint(bb.x), __float_as_uint(bb.y));
                    mma8(Co, ah[mt][0], ah[mt][1], ah[mt][2], ah[mt][3],
                         __float_as_uint(bb.z), __float_as_uint(bb.w));
                    mma8(Ce, al[mt][0], al[mt][1], al[mt][2], al[mt][3],
                         __float_as_uint(bb.x), __float_as_uint(bb.y));
                    mma8(Co, al[mt][0], al[mt][1], al[mt][2], al[mt][3],
                         __float_as_uint(bb.z), __float_as_uint(bb.w));
                }
            }
        }
#pragma unroll 4
        for (int kk = 0; kk < 16; kk++) {
            unsigned ah[2][4];
#pragma unroll
            for (int mt = 0; mt < 2; mt++) {
                int r0 = wm * 32 + mt * 16 + gid;
                int r1 = r0 + 8;
                ah[mt][0] = tf32r(As[r0 * 132 + kk * 8 + tig]);
                ah[mt][1] = tf32r(As[r1 * 132 + kk * 8 + tig]);
                ah[mt][2] = tf32r(As[r0 * 132 + kk * 8 + tig + 4]);
                ah[mt][3] = tf32r(As[r1 * 132 + kk * 8 + tig + 4]);
            }
#pragma unroll
            for (int jp = 0; jp < 2; jp++) {
                int chunk = (s * 16 + kk) * 8 + wn * 2 + jp;
                float4 bb = *(const float4*)(Blo + ((size_t)chunk << 7) + lane * 4);
#pragma unroll
                for (int mt = 0; mt < 2; mt++) {
                    mma8(C + (mt * 4 + jp * 2) * 4, ah[mt][0], ah[mt][1], ah[mt][2], ah[mt][3],
                         __float_as_uint(bb.x), __float_as_uint(bb.y));
                    mma8(C + (mt * 4 + jp * 2 + 1) * 4, ah[mt][0], ah[mt][1], ah[mt][2], ah[mt][3],
                         __float_as_uint(bb.z), __float_as_uint(bb.w));
                }
            }
        }
    }

#pragma unroll
    for (int mt = 0; mt < 2; mt++) {
        int r0 = bx * 64 + wm * 32 + mt * 16 + gid;
        int r1 = r0 + 8;
        float dg0 = (r0 < NN) ? (float)deg[r0] : 0.f;
        float dg1 = (r1 < NN) ? (float)deg[r1] : 0.f;
#pragma unroll
        for (int j = 0; j < 4; j++) {
            int col = wn * 32 + j * 8 + tig * 2;
            float2 bb = *(const float2*)(bn2l + col);
            if (r0 < NN) {
                float2 hh = *(const float2*)(hprev + (size_t)r0 * 128 + col);
                *(float2*)(hn + (size_t)r0 * 128 + col) =
                    make_float2(C[(mt * 4 + j) * 4 + 0] + hh.x + dg0 * bb.x,
                                C[(mt * 4 + j) * 4 + 1] + hh.y + dg0 * bb.y);
            }
            if (r1 < NN) {
                float2 hh = *(const float2*)(hprev + (size_t)r1 * 128 + col);
                *(float2*)(hn + (size_t)r1 * 128 + col) =
                    make_float2(C[(mt * 4 + j) * 4 + 2] + hh.x + dg1 * bb.x,
                                C[(mt * 4 + j) * 4 + 3] + hh.y + dg1 * bb.y);
            }
        }
    }
}

__global__ void ln_kernel(const float* __restrict__ h, const float* __restrict__ x,
                          const float* __restrict__ gamma, const float* __restrict__ beta,
                          float* __restrict__ out)
{
    int g = blockIdx.x * blockDim.x + threadIdx.x;
    int w = g >> 5, lane = g & 31;
    if (w < NN) {
        const float* row = h + (size_t)w * CC;
        float v0 = row[lane], v1 = row[lane + 32], v2 = row[lane + 64], v3 = row[lane + 96];
        float s = v0 + v1 + v2 + v3;
#pragma unroll
        for (int o = 16; o > 0; o >>= 1) s += __shfl_xor_sync(0xffffffffu, s, o);
        float mu = s * (1.f / 128.f);
        float d0 = v0 - mu, d1 = v1 - mu, d2 = v2 - mu, d3 = v3 - mu;
        float q = d0 * d0 + d1 * d1 + d2 * d2 + d3 * d3;
#pragma unroll
        for (int o = 16; o > 0; o >>= 1) q += __shfl_xor_sync(0xffffffffu, q, o);
        float rs = rsqrtf(q * (1.f / 128.f) + 1e-5f);
        float* orow = out + (size_t)w * CC;
        orow[lane]      = gamma[lane]      * d0 * rs + beta[lane];
        orow[lane + 32] = gamma[lane + 32] * d1 * rs + beta[lane + 32];
        orow[lane + 64] = gamma[lane + 64] * d2 * rs + beta[lane + 64];
        orow[lane + 96] = gamma[lane + 96] * d3 * rs + beta[lane + 96];
    }
    int stride = gridDim.x * blockDim.x;
    for (int j = g; j < NN * 3; j += stride) out[(size_t)NN * CC + j] = x[j];
}

extern "C" void kernel_launch(void* const* d_in, const int* in_sizes, int n_in,
                              void* d_out, int out_size)
{
    (void)in_sizes; (void)n_in; (void)out_size;
    const float* single = (const float*)d_in[0];
    const float* coords = (const float*)d_in[2];
    const int*   eidx   = (const int*)d_in[3];
    const float* dist   = (const float*)d_in[4];
    const float* We1 = (const float*)d_in[5];
    const float* be1 = (const float*)d_in[6];
    const float* We2 = (const float*)d_in[7];
    const float* be2 = (const float*)d_in[8];
    const float* Wn1 = (const float*)d_in[9];
    const float* bn1 = (const float*)d_in[10];
    const float* Wn2 = (const float*)d_in[11];
    const float* bn2 = (const float*)d_in[12];
    const float* Wc1 = (const float*)d_in[13];
    const float* bc1 = (const float*)d_in[14];
    const float* Wc2 = (const float*)d_in[15];
    const float* gamma = (const float*)d_in[16];
    const float* beta  = (const float*)d_in[17];
    float* out = (float*)d_out;

    float *h, *hn, *x, *xn, *Pf0, *Pf1, *Wsw, *bp, *Bp, *Wn2sw, *aggS, *distS;
    __half *Ph0, *Ph1;
    int *cnt, *off, *srcS, *dstS;
    cudaGetSymbolAddress((void**)&h,     g_h);
    cudaGetSymbolAddress((void**)&hn,    g_hn);
    cudaGetSymbolAddress((void**)&x,     g_x);
    cudaGetSymbolAddress((void**)&xn,    g_xn);
    cudaGetSymbolAddress((void**)&Ph0,   g_Ph0);
    cudaGetSymbolAddress((void**)&Ph1,   g_Ph1);
    cudaGetSymbolAddress((void**)&Pf0,   g_Pf0);
    cudaGetSymbolAddress((void**)&Pf1,   g_Pf1);
    cudaGetSymbolAddress((void**)&Wsw,   g_Wsw);
    cudaGetSymbolAddress((void**)&bp,    g_bp);
    cudaGetSymbolAddress((void**)&Bp,    g_Bp);
    cudaGetSymbolAddress((void**)&Wn2sw, g_Wn2sw);
    cudaGetSymbolAddress((void**)&aggS,  g_aggS);
    cudaGetSymbolAddress((void**)&cnt,   g_cnt);
    cudaGetSymbolAddress((void**)&off,   g_off);
    cudaGetSymbolAddress((void**)&srcS,  g_srcS);
    cudaGetSymbolAddress((void**)&dstS,  g_dstS);
    cudaGetSymbolAddress((void**)&distS, g_distS);

    static cudaStream_t sC = 0;
    static cudaEvent_t evP = 0, evC = 0;
    if (!sC) {
        cudaStreamCreateWithFlags(&sC, cudaStreamNonBlocking);
        cudaEventCreateWithFlags(&evP, cudaEventDisableTiming);
        cudaEventCreateWithFlags(&evC, cudaEventDisableTiming);
    }

    const int* srcI = eidx;
    const int* dstI = eidx + EE;

    prep_kernel<<<8, 256>>>(We2, be2, Wn1, bn1, Wc1, bc1, Wsw, bp);
    prep2_kernel<<<16, 256>>>(Wn1, Wc1, Bp);
    prep3_kernel<<<4, 128>>>(Wn2, Wn2sw);
    cudaMemcpyAsync(h, single, sizeof(float) * NN * CC, cudaMemcpyDeviceToDevice, 0);
    cudaMemcpyAsync(x, coords, sizeof(float) * NN * 3, cudaMemcpyDeviceToDevice, 0);
    cudaMemsetAsync(aggS, 0, sizeof(float) * (size_t)NN * 256, 0);
    cudaMemsetAsync(cnt, 0, sizeof(int) * NN, 0);
    hist_kernel<<<(EE + 255) / 256, 256>>>(dstI, cnt);
    scan_kernel<<<1, 1024>>>(cnt, off);
    scatter_kernel<<<(EE + 255) / 256, 256>>>(srcI, dstI, dist, off, srcS, dstS, distS);

    for (int l = 0; l < 4; l++) {
        __half* Ph = (l & 1) ? Ph1 : Ph0;
        float*  Pf = (l & 1) ? Pf1 : Pf0;
        dim3 gp((NN + 63) / 64, 8);
        proj2_kernel<<<gp, 256>>>(h, Bp + (size_t)l * 4 * 65536, Ph, Pf);
        cudaEventRecord(evP, 0);

        cudaStreamWaitEvent(sC, evP, 0);
        cudaMemcpyAsync(xn, x, sizeof(float) * NN * 3, cudaMemcpyDeviceToDevice, sC);
        edgec_kernel<<<EE / 32, 256, 0, sC>>>(srcS, dstS, distS,
            We1 + l * 64, be1 + l * 64,
            Wsw + (size_t)(2 * l + 1) * 16384, bp + (2 * l + 1) * 256,
            Wc2 + (size_t)l * 256,
            Ph, Pf, x, xn);
        cudaEventRecord(evC, sC);

        edgen_kernel<<<EE / 32, 256>>>(srcS, dstS, distS,
            We1 + l * 64, be1 + l * 64,
            Wsw + (size_t)(2 * l) * 16384, bp + (2 * l) * 256,
            Ph, Pf, aggS);
        nupd2_kernel<<<(NN + 63) / 64, 256>>>(aggS, Wn2sw + (size_t)l * 65536,
                                              bn2 + l * 128, h, cnt, hn);

        float* t;
        t = h; h = hn; hn = t;
        t = x; x = xn; xn = t;
    }
    cudaStreamWaitEvent(0, evC, 0);
    ln_kernel<<<(NN * 32 + 255) / 256, 256>>>(h, x, gamma, beta, out);
}

// round 17
// speedup vs baseline: 1.2692x; 1.2692x over previous
#include <cuda_runtime.h>
#include <cuda_fp16.h>

#define NN 50000
#define EE 400000
#define CC 128

__device__ float  g_h   [NN * CC];
__device__ float  g_hn  [NN * CC];
__device__ float  g_x   [NN * 3];
__device__ float  g_xn  [NN * 3];
__device__ __half g_P0  [(size_t)NN * 1024];
__device__ __half g_P1  [(size_t)NN * 1024];
__device__ float  g_Wsw [8 * 64 * 256];
__device__ float  g_bp  [8 * 256];
__device__ float  g_Bp  [16 * 2 * 32768];
__device__ float  g_Wn2sw[4 * 2 * 32768];
__device__ float  g_aggS[(size_t)NN * 256];
__device__ int    g_cnt [NN];
__device__ int    g_off [NN];
__device__ int    g_srcS[EE];
__device__ int    g_dstS[EE];
__device__ float  g_distS[EE];

// silu via single-MUFU hardware tanh: silu(v) = v * (0.5*tanh(v/2) + 0.5)
__device__ __forceinline__ float siluf(float v) {
    float t;
    asm("tanh.approx.f32 %0, %1;" : "=f"(t) : "f"(v * 0.5f));
    return v * fmaf(0.5f, t, 0.5f);
}

__device__ __forceinline__ unsigned tf32r(float v) {
    unsigned u;
    asm("cvt.rna.tf32.f32 %0, %1;" : "=r"(u) : "f"(v));
    return u;
}

__device__ __forceinline__ void mma8(float* C, unsigned a0, unsigned a1, unsigned a2, unsigned a3,
                                     unsigned b0, unsigned b1) {
    asm volatile("mma.sync.aligned.m16n8k8.row.col.f32.tf32.tf32.f32 "
                 "{%0,%1,%2,%3}, {%4,%5,%6,%7}, {%8,%9}, {%0,%1,%2,%3};"
                 : "+f"(C[0]), "+f"(C[1]), "+f"(C[2]), "+f"(C[3])
                 : "r"(a0), "r"(a1), "r"(a2), "r"(a3), "r"(b0), "r"(b1));
}

__device__ __forceinline__ void redv2(float* addr, float v0, float v1) {
    asm volatile("red.global.add.v2.f32 [%0], {%1,%2};" :: "l"(addr), "f"(v0), "f"(v1) : "memory");
}

__device__ __forceinline__ int bswz(int k, int n) {
    return (((k >> 3) * 16 + (n >> 4)) << 7)
         + ((n & 7) << 4) + ((k & 3) << 2) + (((n >> 3) & 1) << 1) + ((k >> 2) & 1);
}
__device__ __forceinline__ int bswz128(int k, int n) {
    return (((k >> 3) * 8 + (n >> 4)) << 7)
         + ((n & 7) << 4) + ((k & 3) << 2) + (((n >> 3) & 1) << 1) + ((k >> 2) & 1);
}

// ---------- sort by dst ----------
__global__ void hist_kernel(const int* __restrict__ dstIdx, int* __restrict__ cnt) {
    int e = blockIdx.x * blockDim.x + threadIdx.x;
    if (e < EE) atomicAdd(&cnt[dstIdx[e]], 1);
}

__global__ void scan_kernel(const int* __restrict__ cnt, int* __restrict__ off) {
    __shared__ int sa[1024], sb[1024];
    int t = threadIdx.x;
    int base = t * 49;
    int s = 0;
    for (int i = 0; i < 49; i++) { int r = base + i; if (r < NN) s += cnt[r]; }
    sa[t] = s;
    __syncthreads();
    int* in = sa; int* out = sb;
    for (int d = 1; d < 1024; d <<= 1) {
        out[t] = (t >= d) ? in[t] + in[t - d] : in[t];
        __syncthreads();
        int* tmp = in; in = out; out = tmp;
    }
    int run = (t > 0) ? in[t - 1] : 0;
    for (int i = 0; i < 49; i++) {
        int r = base + i;
        if (r < NN) { off[r] = run; run += cnt[r]; }
    }
}

__global__ void scatter_kernel(const int* __restrict__ srcIdx, const int* __restrict__ dstIdx,
                               const float* __restrict__ dist, int* __restrict__ off,
                               int* __restrict__ srcS, int* __restrict__ dstS,
                               float* __restrict__ distS) {
    int e = blockIdx.x * blockDim.x + threadIdx.x;
    if (e < EE) {
        int d = dstIdx[e];
        int pos = atomicAdd(&off[d], 1);
        int blk = pos >> 5, r = pos & 31;
        int mt = r >> 4, j = r & 15;
        int nr = mt * 16 + ((j & 1) << 3) + (j >> 1);
        int p = blk * 32 + nr;
        srcS[p] = srcIdx[e];
        dstS[p] = d;
        distS[p] = dist[e];
    }
}

// ---------- prep kernels ----------
__global__ void prep_kernel(const float* __restrict__ We2, const float* __restrict__ be2,
                            const float* __restrict__ Wn1, const float* __restrict__ bn1,
                            const float* __restrict__ Wc1, const float* __restrict__ bc1,
                            float* __restrict__ Wsw, float* __restrict__ bp)
{
    int b = blockIdx.x, l = b >> 1, path = b & 1;
    const float* W1 = (path ? Wc1 : Wn1) + (size_t)l * 320 * 256;
    const float* bb = (path ? bc1 : bn1) + l * 256;
    const float* W2 = We2 + l * 64 * 64;
    const float* b2 = be2 + l * 64;
    int c = threadIdx.x;
    float acc[64];
#pragma unroll
    for (int k = 0; k < 64; k++) acc[k] = 0.f;
    float bacc = bb[c];
    for (int q = 0; q < 64; q++) {
        float w = W1[(size_t)(256 + q) * 256 + c];
        bacc += b2[q] * w;
#pragma unroll
        for (int k = 0; k < 64; k++) acc[k] += W2[k * 64 + q] * w;
    }
#pragma unroll
    for (int k = 0; k < 64; k++)
        Wsw[(size_t)b * 16384 + bswz(k, c)] = __uint_as_float(tf32r(acc[k]));
    bp[b * 256 + c] = bacc;
}

__global__ void prep2_kernel(const float* __restrict__ Wn1, const float* __restrict__ Wc1,
                             float* __restrict__ Bp)
{
    int b = blockIdx.x;
    int l = b >> 2, q = b & 3;
    const float* W = (q < 2 ? Wn1 : Wc1) + (size_t)l * 320 * 256 + (size_t)((q & 1) * 128) * 256;
    int c = threadIdx.x;
    float* hiP = Bp + (size_t)b * 65536;
    float* loP = hiP + 32768;
    for (int k = 0; k < 128; k++) {
        float v = W[(size_t)k * 256 + c];
        float hf = __uint_as_float(tf32r(v));
        unsigned lo = tf32r(v - hf);
        int idx = bswz(k, c);
        hiP[idx] = hf;
        loP[idx] = __uint_as_float(lo);
    }
}

__global__ void prep3_kernel(const float* __restrict__ Wn2, float* __restrict__ Wn2sw)
{
    int l = blockIdx.x;
    const float* W = Wn2 + (size_t)l * 256 * 128;
    float* hiP = Wn2sw + (size_t)l * 65536;
    float* loP = hiP + 32768;
    int c = threadIdx.x;
    for (int k = 0; k < 256; k++) {
        float v = W[(size_t)k * 128 + c];
        float hf = __uint_as_float(tf32r(v));
        unsigned lo = tf32r(v - hf);
        int idx = bswz128(k, c);
        hiP[idx] = hf;
        loP[idx] = __uint_as_float(lo);
    }
}

// ---------- proj via TF32 mma; P stored fp16 ----------
__global__ void __launch_bounds__(256) proj2_kernel(const float* __restrict__ h,
                                                    const float* __restrict__ Bl,
                                                    __half* __restrict__ P)
{
    __shared__ float As[64 * 132];
    int bx = blockIdx.x;
    int q = blockIdx.y >> 1, half = blockIdx.y & 1;
    int tid = threadIdx.x;
    int lane = tid & 31, w = tid >> 5;
    int wm = w & 1, wn = w >> 1;
    int gid = lane >> 2, tig = lane & 3;

#pragma unroll
    for (int i = 0; i < 8; i++) {
        int f = i * 256 + tid;
        int row = f >> 5, c4 = (f & 31) << 2;
        int grow = bx * 64 + row;
        float4 v = make_float4(0.f, 0.f, 0.f, 0.f);
        if (grow < NN) v = *(const float4*)(h + (size_t)grow * 128 + c4);
        *(float4*)(As + row * 132 + c4) = v;
    }
    __syncthreads();

    const float* Bhi = Bl + (size_t)q * 65536;
    const float* Blo = Bhi + 32768;
    float C[32];
#pragma unroll
    for (int i = 0; i < 32; i++) C[i] = 0.f;

#pragma unroll 4
    for (int kk = 0; kk < 16; kk++) {
        unsigned ah[2][4], al[2][4];
#pragma unroll
        for (int mt = 0; mt < 2; mt++) {
            int r0 = wm * 32 + mt * 16 + gid;
            int r1 = r0 + 8;
            float v00 = As[r0 * 132 + kk * 8 + tig];
            float v10 = As[r1 * 132 + kk * 8 + tig];
            float v01 = As[r0 * 132 + kk * 8 + tig + 4];
            float v11 = As[r1 * 132 + kk * 8 + tig + 4];
            ah[mt][0] = tf32r(v00); ah[mt][1] = tf32r(v10);
            ah[mt][2] = tf32r(v01); ah[mt][3] = tf32r(v11);
            al[mt][0] = tf32r(v00 - __uint_as_float(ah[mt][0]));
            al[mt][1] = tf32r(v10 - __uint_as_float(ah[mt][1]));
            al[mt][2] = tf32r(v01 - __uint_as_float(ah[mt][2]));
            al[mt][3] = tf32r(v11 - __uint_as_float(ah[mt][3]));
        }
#pragma unroll
        for (int jp = 0; jp < 2; jp++) {
            float4 bb = *(const float4*)(Bhi + ((size_t)(kk * 16 + half * 8 + wn * 2 + jp) << 7) + lane * 4);
#pragma unroll
            for (int mt = 0; mt < 2; mt++) {
                float* Ce = C + (mt * 4 + jp * 2) * 4;
                float* Co = C + (mt * 4 + jp * 2 + 1) * 4;
                mma8(Ce, ah[mt][0], ah[mt][1], ah[mt][2], ah[mt][3],
                     __float_as_uint(bb.x), __float_as_uint(bb.y));
                mma8(Co, ah[mt][0], ah[mt][1], ah[mt][2], ah[mt][3],
                     __float_as_uint(bb.z), __float_as_uint(bb.w));
                mma8(Ce, al[mt][0], al[mt][1], al[mt][2], al[mt][3],
                     __float_as_uint(bb.x), __float_as_uint(bb.y));
                mma8(Co, al[mt][0], al[mt][1], al[mt][2], al[mt][3],
                     __float_as_uint(bb.z), __float_as_uint(bb.w));
            }
        }
    }
#pragma unroll 4
    for (int kk = 0; kk < 16; kk++) {
        unsigned ah[2][4];
#pragma unroll
        for (int mt = 0; mt < 2; mt++) {
            int r0 = wm * 32 + mt * 16 + gid;
            int r1 = r0 + 8;
            ah[mt][0] = tf32r(As[r0 * 132 + kk * 8 + tig]);
            ah[mt][1] = tf32r(As[r1 * 132 + kk * 8 + tig]);
            ah[mt][2] = tf32r(As[r0 * 132 + kk * 8 + tig + 4]);
            ah[mt][3] = tf32r(As[r1 * 132 + kk * 8 + tig + 4]);
        }
#pragma unroll
        for (int jp = 0; jp < 2; jp++) {
            float4 bb = *(const float4*)(Blo + ((size_t)(kk * 16 + half * 8 + wn * 2 + jp) << 7) + lane * 4);
#pragma unroll
            for (int mt = 0; mt < 2; mt++) {
                mma8(C + (mt * 4 + jp * 2) * 4, ah[mt][0], ah[mt][1], ah[mt][2], ah[mt][3],
                     __float_as_uint(bb.x), __float_as_uint(bb.y));
                mma8(C + (mt * 4 + jp * 2 + 1) * 4, ah[mt][0], ah[mt][1], ah[mt][2], ah[mt][3],
                     __float_as_uint(bb.z), __float_as_uint(bb.w));
            }
        }
    }

#pragma unroll
    for (int mt = 0; mt < 2; mt++) {
        int r0 = bx * 64 + wm * 32 + mt * 16 + gid;
        int r1 = r0 + 8;
#pragma unroll
        for (int j = 0; j < 4; j++) {
            int col = q * 256 + half * 128 + wn * 32 + j * 8 + tig * 2;
            if (r0 < NN)
                *(__half2*)(P + (size_t)r0 * 1024 + col) =
                    __floats2half2_rn(C[(mt * 4 + j) * 4 + 0], C[(mt * 4 + j) * 4 + 1]);
            if (r1 < NN)
                *(__half2*)(P + (size_t)r1 * 1024 + col) =
                    __floats2half2_rn(C[(mt * 4 + j) * 4 + 2], C[(mt * 4 + j) * 4 + 3]);
        }
    }
}

// ---------- path n edge kernel (fp16 P gathers) ----------
__global__ void __launch_bounds__(256, 4) edgen_kernel(
    const int* __restrict__ srcS, const int* __restrict__ dstS,
    const float* __restrict__ distS,
    const float* __restrict__ We1l, const float* __restrict__ be1l,
    const float* __restrict__ Wswn, const float* __restrict__ bpn,
    const __half* __restrict__ P, float* __restrict__ aggS)
{
    __shared__ float Ea[32 * 68];
    __shared__ float bpS[256];
    __shared__ int sIdx[32], dIdx[32];

    int tid = threadIdx.x;
    int lane = tid & 31, w = tid >> 5;
    int mt = w & 1, nt = w >> 1;
    int gid = lane >> 2, tig = lane & 3;
    int e0 = blockIdx.x * 32;

    if (tid < 32) { sIdx[tid] = srcS[e0 + tid]; dIdx[tid] = dstS[e0 + tid]; }
    bpS[tid] = bpn[tid];
    {
        int m = tid >> 3, seg = tid & 7;
        float d = distS[e0 + m];
#pragma unroll
        for (int kk = 0; kk < 8; kk++) {
            int k = seg * 8 + kk;
            Ea[m * 68 + k] = __uint_as_float(tf32r(siluf(fmaf(d, We1l[k], be1l[k]))));
        }
    }
    __syncthreads();

    int r0 = mt * 16 + gid, r1 = r0 + 8;
    int s0 = sIdx[r0], d0 = dIdx[r0];
    int s1 = sIdx[r1], d1 = dIdx[r1];

    float C[32];
#pragma unroll
    for (int i = 0; i < 32; i++) C[i] = 0.f;
#pragma unroll
    for (int kk = 0; kk < 8; kk++) {
        unsigned a0 = __float_as_uint(Ea[r0 * 68 + kk * 8 + tig]);
        unsigned a1 = __float_as_uint(Ea[r1 * 68 + kk * 8 + tig]);
        unsigned a2 = __float_as_uint(Ea[r0 * 68 + kk * 8 + tig + 4]);
        unsigned a3 = __float_as_uint(Ea[r1 * 68 + kk * 8 + tig + 4]);
#pragma unroll
        for (int jp = 0; jp < 4; jp++) {
            float4 bb = *(const float4*)(Wswn + ((size_t)(kk * 16 + nt * 4 + jp) << 7) + lane * 4);
            mma8(C + (jp * 2) * 4, a0, a1, a2, a3, __float_as_uint(bb.x), __float_as_uint(bb.y));
            mma8(C + (jp * 2 + 1) * 4, a0, a1, a2, a3, __float_as_uint(bb.z), __float_as_uint(bb.w));
        }
    }
#pragma unroll
    for (int j = 0; j < 8; j++) {
        int cc = (nt * 8 + j) * 8 + tig * 2;
        float2 bb = *(const float2*)(bpS + cc);
        float2 ps = __half22float2(*(const __half2*)(P + (size_t)s0 * 1024 + cc));
        float2 pd = __half22float2(*(const __half2*)(P + (size_t)d0 * 1024 + 256 + cc));
        float v0 = siluf(C[j * 4 + 0] + bb.x + ps.x + pd.x);
        float v1 = siluf(C[j * 4 + 1] + bb.y + ps.y + pd.y);
        ps = __half22float2(*(const __half2*)(P + (size_t)s1 * 1024 + cc));
        pd = __half22float2(*(const __half2*)(P + (size_t)d1 * 1024 + 256 + cc));
        float w0 = siluf(C[j * 4 + 2] + bb.x + ps.x + pd.x);
        float w1 = siluf(C[j * 4 + 3] + bb.y + ps.y + pd.y);
        if (d0 == d1) {
            redv2(aggS + (size_t)d0 * 256 + cc, v0 + w0, v1 + w1);
        } else {
            redv2(aggS + (size_t)d0 * 256 + cc, v0, v1);
            redv2(aggS + (size_t)d1 * 256 + cc, w0, w1);
        }
    }
}

// ---------- path c edge kernel (fp16 P gathers) ----------
__global__ void __launch_bounds__(256, 4) edgec_kernel(
    const int* __restrict__ srcS, const int* __restrict__ dstS,
    const float* __restrict__ distS,
    const float* __restrict__ We1l, const float* __restrict__ be1l,
    const float* __restrict__ Wswc, const float* __restrict__ bpc,
    const float* __restrict__ Wc2l,
    const __half* __restrict__ P, const float* __restrict__ x,
    float* __restrict__ xn)
{
    __shared__ float Ea[32 * 68];
    __shared__ float bpS[256];
    __shared__ float Wc2s[256];
    __shared__ float cwP[128];
    __shared__ int sIdx[32], dIdx[32];

    int tid = threadIdx.x;
    int lane = tid & 31, w = tid >> 5;
    int mt = w & 1, nt = w >> 1;
    int gid = lane >> 2, tig = lane & 3;
    int e0 = blockIdx.x * 32;

    if (tid < 32) { sIdx[tid] = srcS[e0 + tid]; dIdx[tid] = dstS[e0 + tid]; }
    bpS[tid] = bpc[tid];
    Wc2s[tid] = Wc2l[tid];
    {
        int m = tid >> 3, seg = tid & 7;
        float d = distS[e0 + m];
#pragma unroll
        for (int kk = 0; kk < 8; kk++) {
            int k = seg * 8 + kk;
            Ea[m * 68 + k] = __uint_as_float(tf32r(siluf(fmaf(d, We1l[k], be1l[k]))));
        }
    }
    __syncthreads();

    int r0 = mt * 16 + gid, r1 = r0 + 8;
    int s0 = sIdx[r0], d0 = dIdx[r0];
    int s1 = sIdx[r1], d1 = dIdx[r1];

    float C[32];
#pragma unroll
    for (int i = 0; i < 32; i++) C[i] = 0.f;
#pragma unroll
    for (int kk = 0; kk < 8; kk++) {
        unsigned a0 = __float_as_uint(Ea[r0 * 68 + kk * 8 + tig]);
        unsigned a1 = __float_as_uint(Ea[r1 * 68 + kk * 8 + tig]);
        unsigned a2 = __float_as_uint(Ea[r0 * 68 + kk * 8 + tig + 4]);
        unsigned a3 = __float_as_uint(Ea[r1 * 68 + kk * 8 + tig + 4]);
#pragma unroll
        for (int jp = 0; jp < 4; jp++) {
            float4 bb = *(const float4*)(Wswc + ((size_t)(kk * 16 + nt * 4 + jp) << 7) + lane * 4);
            mma8(C + (jp * 2) * 4, a0, a1, a2, a3, __float_as_uint(bb.x), __float_as_uint(bb.y));
            mma8(C + (jp * 2 + 1) * 4, a0, a1, a2, a3, __float_as_uint(bb.z), __float_as_uint(bb.w));
        }
    }
    float p0 = 0.f, p1 = 0.f;
#pragma unroll
    for (int j = 0; j < 8; j++) {
        int cc = (nt * 8 + j) * 8 + tig * 2;
        float2 bb = *(const float2*)(bpS + cc);
        float2 wc = *(const float2*)(Wc2s + cc);
        float2 ps = __half22float2(*(const __half2*)(P + (size_t)s0 * 1024 + 512 + cc));
        float2 pd = __half22float2(*(const __half2*)(P + (size_t)d0 * 1024 + 768 + cc));
        p0 += siluf(C[j * 4 + 0] + bb.x + ps.x + pd.x) * wc.x
            + siluf(C[j * 4 + 1] + bb.y + ps.y + pd.y) * wc.y;
        ps = __half22float2(*(const __half2*)(P + (size_t)s1 * 1024 + 512 + cc));
        pd = __half22float2(*(const __half2*)(P + (size_t)d1 * 1024 + 768 + cc));
        p1 += siluf(C[j * 4 + 2] + bb.x + ps.x + pd.x) * wc.x
            + siluf(C[j * 4 + 3] + bb.y + ps.y + pd.y) * wc.y;
    }
    p0 += __shfl_xor_sync(0xffffffffu, p0, 1);
    p0 += __shfl_xor_sync(0xffffffffu, p0, 2);
    p1 += __shfl_xor_sync(0xffffffffu, p1, 1);
    p1 += __shfl_xor_sync(0xffffffffu, p1, 2);
    if (tig == 0) {
        cwP[r0 * 4 + nt] = p0;
        cwP[r1 * 4 + nt] = p1;
    }
    __syncthreads();
    if (tid < 32) {
        float cw = cwP[tid * 4] + cwP[tid * 4 + 1] + cwP[tid * 4 + 2] + cwP[tid * 4 + 3];
        int s = sIdx[tid], dd = dIdx[tid];
        float u0 = cw * (x[(size_t)s * 3 + 0] - x[(size_t)dd * 3 + 0]);
        float u1 = cw * (x[(size_t)s * 3 + 1] - x[(size_t)dd * 3 + 1]);
        float u2 = cw * (x[(size_t)s * 3 + 2] - x[(size_t)dd * 3 + 2]);
        atomicAdd(&xn[(size_t)dd * 3 + 0], u0);
        atomicAdd(&xn[(size_t)dd * 3 + 1], u1);
        atomicAdd(&xn[(size_t)dd * 3 + 2], u2);
    }
}

// ---------- nupd2: hn = h + aggS @ Wn2 + deg*bn2 via TF32 hi/lo mma ----------
__global__ void __launch_bounds__(256) nupd2_kernel(const float* __restrict__ A,
                                                    const float* __restrict__ Bl,
                                                    const float* __restrict__ bn2l,
                                                    const float* __restrict__ hprev,
                                                    const int* __restrict__ deg,
                                                    float* __restrict__ hn)
{
    __shared__ float As[64 * 132];
    int bx = blockIdx.x;
    int tid = threadIdx.x;
    int lane = tid & 31, w = tid >> 5;
    int wm = w & 1, wn = w >> 1;
    int gid = lane >> 2, tig = lane & 3;

    const float* Bhi = Bl;
    const float* Blo = Bl + 32768;
    float C[32];
#pragma unroll
    for (int i = 0; i < 32; i++) C[i] = 0.f;

#pragma unroll
    for (int s = 0; s < 2; s++) {
        __syncthreads();
#pragma unroll
        for (int i = 0; i < 8; i++) {
            int f = i * 256 + tid;
            int row = f >> 5, c4 = (f & 31) << 2;
            int grow = bx * 64 + row;
            float4 v = make_float4(0.f, 0.f, 0.f, 0.f);
            if (grow < NN) v = *(const float4*)(A + (size_t)grow * 256 + s * 128 + c4);
            *(float4*)(As + row * 132 + c4) = v;
        }
        __syncthreads();

#pragma unroll 4
        for (int kk = 0; kk < 16; kk++) {
            unsigned ah[2][4], al[2][4];
#pragma unroll
            for (int mt = 0; mt < 2; mt++) {
                int r0 = wm * 32 + mt * 16 + gid;
                int r1 = r0 + 8;
                float v00 = As[r0 * 132 + kk * 8 + tig];
                float v10 = As[r1 * 132 + kk * 8 + tig];
                float v01 = As[r0 * 132 + kk * 8 + tig + 4];
                float v11 = As[r1 * 132 + kk * 8 + tig + 4];
                ah[mt][0] = tf32r(v00); ah[mt][1] = tf32r(v10);
                ah[mt][2] = tf32r(v01); ah[mt][3] = tf32r(v11);
                al[mt][0] = tf32r(v00 - __uint_as_float(ah[mt][0]));
                al[mt][1] = tf32r(v10 - __uint_as_float(ah[mt][1]));
                al[mt][2] = tf32r(v01 - __uint_as_float(ah[mt][2]));
                al[mt][3] = tf32r(v11 - __uint_as_float(ah[mt][3]));
            }
#pragma unroll
            for (int jp = 0; jp < 2; jp++) {
                int chunk = (s * 16 + kk) * 8 + wn * 2 + jp;
                float4 bb = *(const float4*)(Bhi + ((size_t)chunk << 7) + lane * 4);
#pragma unroll
                for (int mt = 0; mt < 2; mt++) {
                    float* Ce = C + (mt * 4 + jp * 2) * 4;
                    float* Co = C + (mt * 4 + jp * 2 + 1) * 4;
                    mma8(Ce, ah[mt][0], ah[mt][1], ah[mt][2], ah[mt][3],
                         __float_as_uint(bb.x), __float_as_uint(bb.y));
                    mma8(Co, ah[mt][0], ah[mt][1], ah[mt][2], ah[mt][3],
                         __float_as_uint(bb.z), __float_as_uint(bb.w));
                    mma8(Ce, al[mt][0], al[mt][1], al[mt][2], al[mt][3],
                         __float_as_uint(bb.x), __float_as_uint(bb.y));
                    mma8(Co, al[mt][0], al[mt][1], al[mt][2], al[mt][3],
                         __float_as_uint(bb.z), __float_as_uint(bb.w));
                }
            }
        }
#pragma unroll 4
        for (int kk = 0; kk < 16; kk++) {
            unsigned ah[2][4];
#pragma unroll
            for (int mt = 0; mt < 2; mt++) {
                int r0 = wm * 32 + mt * 16 + gid;
                int r1 = r0 + 8;
                ah[mt][0] = tf32r(As[r0 * 132 + kk * 8 + tig]);
                ah[mt][1] = tf32r(As[r1 * 132 + kk * 8 + tig]);
                ah[mt][2] = tf32r(As[r0 * 132 + kk * 8 + tig + 4]);
                ah[mt][3] = tf32r(As[r1 * 132 + kk * 8 + tig + 4]);
            }
#pragma unroll
            for (int jp = 0; jp < 2; jp++) {
                int chunk = (s * 16 + kk) * 8 + wn * 2 + jp;
                float4 bb = *(const float4*)(Blo + ((size_t)chunk << 7) + lane * 4);
#pragma unroll
                for (int mt = 0; mt < 2; mt++) {
                    mma8(C + (mt * 4 + jp * 2) * 4, ah[mt][0], ah[mt][1], ah[mt][2], ah[mt][3],
                         __float_as_uint(bb.x), __float_as_uint(bb.y));
                    mma8(C + (mt * 4 + jp * 2 + 1) * 4, ah[mt][0], ah[mt][1], ah[mt][2], ah[mt][3],
                         __float_as_uint(bb.z), __float_as_uint(bb.w));
                }
            }
        }
    }

#pragma unroll
    for (int mt = 0; mt < 2; mt++) {
        int r0 = bx * 64 + wm * 32 + mt * 16 + gid;
        int r1 = r0 + 8;
        float dg0 = (r0 < NN) ? (float)deg[r0] : 0.f;
        float dg1 = (r1 < NN) ? (float)deg[r1] : 0.f;
#pragma unroll
        for (int j = 0; j < 4; j++) {
            int col = wn * 32 + j * 8 + tig * 2;
            float2 bb = *(const float2*)(bn2l + col);
            if (r0 < NN) {
                float2 hh = *(const float2*)(hprev + (size_t)r0 * 128 + col);
                *(float2*)(hn + (size_t)r0 * 128 + col) =
                    make_float2(C[(mt * 4 + j) * 4 + 0] + hh.x + dg0 * bb.x,
                                C[(mt * 4 + j) * 4 + 1] + hh.y + dg0 * bb.y);
            }
            if (r1 < NN) {
                float2 hh = *(const float2*)(hprev + (size_t)r1 * 128 + col);
                *(float2*)(hn + (size_t)r1 * 128 + col) =
                    make_float2(C[(mt * 4 + j) * 4 + 2] + hh.x + dg1 * bb.x,
                                C[(mt * 4 + j) * 4 + 3] + hh.y + dg1 * bb.y);
            }
        }
    }
}

__global__ void ln_kernel(const float* __restrict__ h, const float* __restrict__ x,
                          const float* __restrict__ gamma, const float* __restrict__ beta,
                          float* __restrict__ out)
{
    int g = blockIdx.x * blockDim.x + threadIdx.x;
    int w = g >> 5, lane = g & 31;
    if (w < NN) {
        const float* row = h + (size_t)w * CC;
        float v0 = row[lane], v1 = row[lane + 32], v2 = row[lane + 64], v3 = row[lane + 96];
        float s = v0 + v1 + v2 + v3;
#pragma unroll
        for (int o = 16; o > 0; o >>= 1) s += __shfl_xor_sync(0xffffffffu, s, o);
        float mu = s * (1.f / 128.f);
        float d0 = v0 - mu, d1 = v1 - mu, d2 = v2 - mu, d3 = v3 - mu;
        float q = d0 * d0 + d1 * d1 + d2 * d2 + d3 * d3;
#pragma unroll
        for (int o = 16; o > 0; o >>= 1) q += __shfl_xor_sync(0xffffffffu, q, o);
        float rs = rsqrtf(q * (1.f / 128.f) + 1e-5f);
        float* orow = out + (size_t)w * CC;
        orow[lane]      = gamma[lane]      * d0 * rs + beta[lane];
        orow[lane + 32] = gamma[lane + 32] * d1 * rs + beta[lane + 32];
        orow[lane + 64] = gamma[lane + 64] * d2 * rs + beta[lane + 64];
        orow[lane + 96] = gamma[lane + 96] * d3 * rs + beta[lane + 96];
    }
    int stride = gridDim.x * blockDim.x;
    for (int j = g; j < NN * 3; j += stride) out[(size_t)NN * CC + j] = x[j];
}

extern "C" void kernel_launch(void* const* d_in, const int* in_sizes, int n_in,
                              void* d_out, int out_size)
{
    (void)in_sizes; (void)n_in; (void)out_size;
    const float* single = (const float*)d_in[0];
    const float* coords = (const float*)d_in[2];
    const int*   eidx   = (const int*)d_in[3];
    const float* dist   = (const float*)d_in[4];
    const float* We1 = (const float*)d_in[5];
    const float* be1 = (const float*)d_in[6];
    const float* We2 = (const float*)d_in[7];
    const float* be2 = (const float*)d_in[8];
    const float* Wn1 = (const float*)d_in[9];
    const float* bn1 = (const float*)d_in[10];
    const float* Wn2 = (const float*)d_in[11];
    const float* bn2 = (const float*)d_in[12];
    const float* Wc1 = (const float*)d_in[13];
    const float* bc1 = (const float*)d_in[14];
    const float* Wc2 = (const float*)d_in[15];
    const float* gamma = (const float*)d_in[16];
    const float* beta  = (const float*)d_in[17];
    float* out = (float*)d_out;

    float *h, *hn, *x, *xn, *Wsw, *bp, *Bp, *Wn2sw, *aggS, *distS;
    __half *P0, *P1;
    int *cnt, *off, *srcS, *dstS;
    cudaGetSymbolAddress((void**)&h,     g_h);
    cudaGetSymbolAddress((void**)&hn,    g_hn);
    cudaGetSymbolAddress((void**)&x,     g_x);
    cudaGetSymbolAddress((void**)&xn,    g_xn);
    cudaGetSymbolAddress((void**)&P0,    g_P0);
    cudaGetSymbolAddress((void**)&P1,    g_P1);
    cudaGetSymbolAddress((void**)&Wsw,   g_Wsw);
    cudaGetSymbolAddress((void**)&bp,    g_bp);
    cudaGetSymbolAddress((void**)&Bp,    g_Bp);
    cudaGetSymbolAddress((void**)&Wn2sw, g_Wn2sw);
    cudaGetSymbolAddress((void**)&aggS,  g_aggS);
    cudaGetSymbolAddress((void**)&cnt,   g_cnt);
    cudaGetSymbolAddress((void**)&off,   g_off);
    cudaGetSymbolAddress((void**)&srcS,  g_srcS);
    cudaGetSymbolAddress((void**)&dstS,  g_dstS);
    cudaGetSymbolAddress((void**)&distS, g_distS);

    static cudaStream_t sC = 0;
    static cudaEvent_t evP = 0, evC = 0, evN = 0, evZ = 0;
    if (!sC) {
        cudaStreamCreateWithFlags(&sC, cudaStreamNonBlocking);
        cudaEventCreateWithFlags(&evP, cudaEventDisableTiming);
        cudaEventCreateWithFlags(&evC, cudaEventDisableTiming);
        cudaEventCreateWithFlags(&evN, cudaEventDisableTiming);
        cudaEventCreateWithFlags(&evZ, cudaEventDisableTiming);
    }

    const int* srcI = eidx;
    const int* dstI = eidx + EE;

    prep_kernel<<<8, 256>>>(We2, be2, Wn1, bn1, Wc1, bc1, Wsw, bp);
    prep2_kernel<<<16, 256>>>(Wn1, Wc1, Bp);
    prep3_kernel<<<4, 128>>>(Wn2, Wn2sw);
    cudaMemcpyAsync(h, single, sizeof(float) * NN * CC, cudaMemcpyDeviceToDevice, 0);
    cudaMemcpyAsync(x, coords, sizeof(float) * NN * 3, cudaMemcpyDeviceToDevice, 0);
    cudaMemsetAsync(aggS, 0, sizeof(float) * (size_t)NN * 256, 0);
    cudaMemsetAsync(cnt, 0, sizeof(int) * NN, 0);
    hist_kernel<<<(EE + 255) / 256, 256>>>(dstI, cnt);
    scan_kernel<<<1, 1024>>>(cnt, off);
    scatter_kernel<<<(EE + 255) / 256, 256>>>(srcI, dstI, dist, off, srcS, dstS, distS);

    for (int l = 0; l < 4; l++) {
        __half* P = (l & 1) ? P1 : P0;
        dim3 gp((NN + 63) / 64, 8);
        proj2_kernel<<<gp, 256>>>(h, Bp + (size_t)l * 4 * 65536, P);
        cudaEventRecord(evP, 0);

        cudaStreamWaitEvent(sC, evP, 0);
        cudaMemcpyAsync(xn, x, sizeof(float) * NN * 3, cudaMemcpyDeviceToDevice, sC);
        edgec_kernel<<<EE / 32, 256, 0, sC>>>(srcS, dstS, distS,
            We1 + l * 64, be1 + l * 64,
            Wsw + (size_t)(2 * l + 1) * 16384, bp + (2 * l + 1) * 256,
            Wc2 + (size_t)l * 256,
            P, x, xn);
        cudaEventRecord(evC, sC);

        // wait for the off-stream aggS zeroing from the previous layer
        if (l > 0) cudaStreamWaitEvent(0, evZ, 0);
        edgen_kernel<<<EE / 32, 256>>>(srcS, dstS, distS,
            We1 + l * 64, be1 + l * 64,
            Wsw + (size_t)(2 * l) * 16384, bp + (2 * l) * 256,
            P, aggS);
        nupd2_kernel<<<(NN + 63) / 64, 256>>>(aggS, Wn2sw + (size_t)l * 65536,
                                              bn2 + l * 128, h, cnt, hn);
        cudaEventRecord(evN, 0);
        if (l < 3) {
            // zero aggS on the side stream, overlapped with next proj2
            cudaStreamWaitEvent(sC, evN, 0);
            cudaMemsetAsync(aggS, 0, sizeof(float) * (size_t)NN * 256, sC);
            cudaEventRecord(evZ, sC);
        }

        float* t;
        t = h; h = hn; hn = t;
        t = x; x = xn; xn = t;
    }
    cudaStreamWaitEvent(0, evC, 0);
    ln_kernel<<<(NN * 32 + 255) / 256, 256>>>(h, x, gamma, beta, out);
}